// round 12
// baseline (speedup 1.0000x reference)
#include <cuda_runtime.h>
#include <cuda_bf16.h>
#include <cstdint>
#include <cstddef>

// RWKV time-mix token-shift block — bf16 HMMA, coalesced-epilogue version.
// out = concat(x_kwvrg[B,S,5,D], new_state[B,66,D])

#define S_LEN 2048
#define D_DIM 2048
#define NST   66
#define NL    160
#define ROWS_MAX 8192

// scratch
__device__ __nv_bfloat16 g_xxxh[ROWS_MAX * NL];      // tanh(xm@W1), bf16
__device__ __nv_bfloat16 g_w1t[NL * D_DIM];          // W1^T [n][k] bf16
__device__ __nv_bfloat16 g_w2t[5 * D_DIM * 32];      // W2^T [f][d][k] bf16

// ---- mma.sync bf16 (m16n8k16, row.col, f32 accum) --------------------------
__device__ __forceinline__ void mma_bf16(float* c,
                                         uint32_t a0, uint32_t a1,
                                         uint32_t a2, uint32_t a3,
                                         uint32_t b0, uint32_t b1) {
    asm volatile(
        "mma.sync.aligned.m16n8k16.row.col.f32.bf16.bf16.f32 "
        "{%0,%1,%2,%3}, {%4,%5,%6,%7}, {%8,%9}, {%0,%1,%2,%3};"
        : "+f"(c[0]), "+f"(c[1]), "+f"(c[2]), "+f"(c[3])
        : "r"(a0), "r"(a1), "r"(a2), "r"(a3), "r"(b0), "r"(b1));
}

__device__ __forceinline__ uint32_t bf2_pack(float lo, float hi) {
    __nv_bfloat162 h = __floats2bfloat162_rn(lo, hi);
    return *(uint32_t*)&h;
}

// ---------------------------------------------------------------------------
// Prep: W1[2048][160] f32 -> g_w1t[160][2048] bf16
// ---------------------------------------------------------------------------
__global__ void w1t_kernel(const float* __restrict__ w1)
{
    __shared__ float t[32][33];
    const int k0 = blockIdx.x * 32;
    const int n0 = blockIdx.y * 32;
    const int tid = threadIdx.x;
    for (int l = tid; l < 1024; l += 256) {
        const int kk = l >> 5, nn = l & 31;
        t[kk][nn] = w1[(size_t)(k0 + kk) * NL + n0 + nn];
    }
    __syncthreads();
    const int nn = tid >> 3;
    const int kc = (tid & 7) * 4;
    uint2 pk;
    pk.x = bf2_pack(t[kc + 0][nn], t[kc + 1][nn]);
    pk.y = bf2_pack(t[kc + 2][nn], t[kc + 3][nn]);
    *(uint2*)&g_w1t[(size_t)(n0 + nn) * D_DIM + k0 + kc] = pk;
}

// ---------------------------------------------------------------------------
// Prep: W2[5][32][2048] f32 -> g_w2t[f][d][k] bf16
// ---------------------------------------------------------------------------
__global__ void w2t_kernel(const float* __restrict__ w2)
{
    __shared__ float t[32][33];
    const int f  = blockIdx.y;
    const int d0 = blockIdx.x * 32;
    const int tid = threadIdx.x;
    for (int l = tid; l < 1024; l += 256) {
        const int kk = l >> 5, dd = l & 31;
        t[kk][dd] = w2[((size_t)f * 32 + kk) * D_DIM + d0 + dd];
    }
    __syncthreads();
    const int dd = tid >> 3;
    const int kc = (tid & 7) * 4;
    uint2 pk;
    pk.x = bf2_pack(t[kc + 0][dd], t[kc + 1][dd]);
    pk.y = bf2_pack(t[kc + 2][dd], t[kc + 3][dd]);
    *(uint2*)&g_w2t[(((size_t)f * D_DIM) + d0 + dd) * 32 + kc] = pk;
}

// ---------------------------------------------------------------------------
// GEMM1: xm = x + (prev - x)*tmx;  g_xxxh = bf16(tanh(xm @ W1))
// CTA: 32 rows x 160 cols, 8 warps (2m x 4n), K chunks of 64,
// register-staged prefetch to hide global latency.
// ---------------------------------------------------------------------------
__global__ __launch_bounds__(256) void gemm1_mma_kernel(
    const float* __restrict__ x, const float* __restrict__ state,
    const float* __restrict__ tmx, const int* __restrict__ ip)
{
    __shared__ __align__(16) __nv_bfloat16 As[32][72];    // xm tile [r][k]
    __shared__ __align__(16) __nv_bfloat16 Bs[NL][72];    // W1^T tile [n][k]

    const int R0 = blockIdx.x * 32;
    const int b  = R0 / S_LEN;
    const int s0 = R0 % S_LEN;
    const int i1 = NST * ip[0] + 1;
    const float* __restrict__ srow = state + ((size_t)b * NST + i1) * D_DIM;

    const int tid  = threadIdx.x;
    const int w    = tid >> 5;
    const int lane = tid & 31;
    const int g    = lane >> 2;
    const int tg   = lane & 3;
    const int mb   = (w >> 2) * 16;
    const int nb   = (w & 3) * 40;

    // loader roles
    const int lr = tid >> 3;
    const int lk = (tid & 7) * 8;
    const int glr = R0 + lr;
    const float* __restrict__ curp = x + (size_t)glr * D_DIM;
    const float* __restrict__ prvp = (s0 == 0 && lr == 0)
        ? srow : x + (size_t)(glr - 1) * D_DIM;
    int nB[5], kB[5];
#pragma unroll
    for (int j = 0; j < 5; j++) {
        const int l = tid + 256 * j;
        nB[j] = l >> 3;
        kB[j] = (l & 7) * 8;
    }

    uint4 aReg;
    uint4 bReg[5];

#define G1_PREFETCH(K0) do {                                                  \
        const float4 c0 = *(const float4*)&curp[(K0) + lk];                   \
        const float4 c1 = *(const float4*)&curp[(K0) + lk + 4];               \
        const float4 p0 = *(const float4*)&prvp[(K0) + lk];                   \
        const float4 p1 = *(const float4*)&prvp[(K0) + lk + 4];               \
        const float4 t0 = *(const float4*)&tmx[(K0) + lk];                    \
        const float4 t1 = *(const float4*)&tmx[(K0) + lk + 4];                \
        aReg.x = bf2_pack(c0.x + (p0.x - c0.x) * t0.x,                        \
                          c0.y + (p0.y - c0.y) * t0.y);                       \
        aReg.y = bf2_pack(c0.z + (p0.z - c0.z) * t0.z,                        \
                          c0.w + (p0.w - c0.w) * t0.w);                       \
        aReg.z = bf2_pack(c1.x + (p1.x - c1.x) * t1.x,                        \
                          c1.y + (p1.y - c1.y) * t1.y);                       \
        aReg.w = bf2_pack(c1.z + (p1.z - c1.z) * t1.z,                        \
                          c1.w + (p1.w - c1.w) * t1.w);                       \
        _Pragma("unroll")                                                     \
        for (int j = 0; j < 5; j++)                                           \
            bReg[j] = *(const uint4*)&g_w1t[(size_t)nB[j] * D_DIM + (K0) + kB[j]]; \
    } while (0)

    float acc[5][4];
#pragma unroll
    for (int j = 0; j < 5; j++)
#pragma unroll
        for (int q = 0; q < 4; q++) acc[j][q] = 0.0f;

    G1_PREFETCH(0);

    for (int i = 0; i < 32; i++) {
        __syncthreads();                 // previous chunk's compute done
        *(uint4*)&As[lr][lk] = aReg;
#pragma unroll
        for (int j = 0; j < 5; j++)
            *(uint4*)&Bs[nB[j]][kB[j]] = bReg[j];
        __syncthreads();
        if (i < 31) G1_PREFETCH((i + 1) * 64);

#pragma unroll
        for (int ks = 0; ks < 4; ks++) {
            const int ko = ks * 16 + tg * 2;
            const uint32_t a0 = *(const uint32_t*)&As[mb + g][ko];
            const uint32_t a1 = *(const uint32_t*)&As[mb + g + 8][ko];
            const uint32_t a2 = *(const uint32_t*)&As[mb + g][ko + 8];
            const uint32_t a3 = *(const uint32_t*)&As[mb + g + 8][ko + 8];
#pragma unroll
            for (int j = 0; j < 5; j++) {
                const int n = nb + j * 8 + g;
                const uint32_t b0 = *(const uint32_t*)&Bs[n][ko];
                const uint32_t b1 = *(const uint32_t*)&Bs[n][ko + 8];
                mma_bf16(acc[j], a0, a1, a2, a3, b0, b1);
            }
        }
    }

    // epilogue: tanh -> bf16
#pragma unroll
    for (int j = 0; j < 5; j++) {
        const int col = nb + j * 8 + tg * 2;
        const size_t rlo = (size_t)(R0 + mb + g) * NL + col;
        const size_t rhi = (size_t)(R0 + mb + g + 8) * NL + col;
        *(uint32_t*)&g_xxxh[rlo] = bf2_pack(tanhf(acc[j][0]), tanhf(acc[j][1]));
        *(uint32_t*)&g_xxxh[rhi] = bf2_pack(tanhf(acc[j][2]), tanhf(acc[j][3]));
    }
#undef G1_PREFETCH
}

// ---------------------------------------------------------------------------
// GEMM2 + epilogue: out[r,f,d] = cur + (prev-cur)*(maa_f[d] + xxx_f @ W2_f)
// CTA: 32 rows x 128 d. Fragment work in smem, epilogue fully coalesced,
// cur/prev held in registers across all 5 modes.
// smem: W2s (8KB, XOR-swizzled), As2 (10.75KB, stride 168), accs (16.1KB,
// chunk-padded [8][516]).
// ---------------------------------------------------------------------------
__global__ __launch_bounds__(256, 2) void gemm2_mma_kernel(
    const float* __restrict__ x, const float* __restrict__ state,
    const float* __restrict__ mk, const float* __restrict__ mw,
    const float* __restrict__ mv, const float* __restrict__ mr,
    const float* __restrict__ mg,
    const int* __restrict__ ip, float* __restrict__ out)
{
    __shared__ __align__(16) uint4 W2s4[512];             // [d][granule], swizzled
    __shared__ __align__(16) __nv_bfloat16 As2[32 * 168]; // xxx rows, stride 168
    __shared__ __align__(16) float accs[8 * 516];         // [chunk][row*16+u]

    const int R0 = blockIdx.x * 32;
    const int d0 = blockIdx.y * 128;
    const int b  = R0 / S_LEN;
    const int s0 = R0 % S_LEN;
    const int i1 = NST * ip[0] + 1;
    const float* __restrict__ srow = state + ((size_t)b * NST + i1) * D_DIM;

    const int tid  = threadIdx.x;
    const int w    = tid >> 5;
    const int lane = tid & 31;
    const int g    = lane >> 2;
    const int tg   = lane & 3;
    const int mb   = (w >> 2) * 16;        // warp row base
    const int dwb  = (w & 3) * 32;         // warp d base (local)

    // ---- epilogue mapping (coalesced): row er, chunk ec of 16 floats ------
    const int er = tid >> 3;
    const int ec = tid & 7;
    const int grE = R0 + er;
    const float* __restrict__ curE = x + (size_t)grE * D_DIM + d0 + ec * 16;
    const float* __restrict__ prvE = (s0 == 0 && er == 0)
        ? srow + d0 + ec * 16 : curE - D_DIM;

    float4 cur4[4], prv4[4];
#pragma unroll
    for (int q = 0; q < 4; q++) {
        cur4[q] = *(const float4*)&curE[q * 4];
        prv4[q] = *(const float4*)&prvE[q * 4];
    }

    // ---- stage xxx rows into As2 (coalesced) ------------------------------
    for (int l = tid; l < 640; l += 256) {
        const int r = l / 20, gi = l % 20;
        *(uint4*)((char*)As2 + r * 336 + gi * 16) =
            *(const uint4*)&g_xxxh[(size_t)(R0 + r) * NL + gi * 8];
    }

    const char* ab = (const char*)As2;
    const char* wb = (const char*)W2s4;

    for (int f = 0; f < 5; f++) {
        // ---- load W2 tile for this mode (coalesced, swizzled) -------------
        for (int l = tid; l < 512; l += 256) {
            const int d = l >> 2, lg = l & 3;
            W2s4[d * 4 + (lg ^ (d & 3))] =
                *(const uint4*)&g_w2t[((size_t)f * D_DIM + d0 + d) * 32 + lg * 8];
        }
        __syncthreads();   // W2s/As2 ready; accs free (prev epilogue done)

        // ---- MMA ----------------------------------------------------------
        float acc[4][4];
#pragma unroll
        for (int j = 0; j < 4; j++)
#pragma unroll
            for (int q = 0; q < 4; q++) acc[j][q] = 0.0f;

#pragma unroll
        for (int ks = 0; ks < 2; ks++) {
            const int ko = f * 32 + ks * 16 + tg * 2;
            const uint32_t a0 = *(const uint32_t*)(ab + (mb + g) * 336 + ko * 2);
            const uint32_t a1 = *(const uint32_t*)(ab + (mb + g + 8) * 336 + ko * 2);
            const uint32_t a2 = *(const uint32_t*)(ab + (mb + g) * 336 + ko * 2 + 16);
            const uint32_t a3 = *(const uint32_t*)(ab + (mb + g + 8) * 336 + ko * 2 + 16);
#pragma unroll
            for (int j = 0; j < 4; j++) {
                const int dl = dwb + j * 8 + g;
                const uint32_t b0 = *(const uint32_t*)
                    (wb + dl * 64 + (((ks * 2)     ^ (dl & 3)) << 4) + tg * 4);
                const uint32_t b1 = *(const uint32_t*)
                    (wb + dl * 64 + (((ks * 2 + 1) ^ (dl & 3)) << 4) + tg * 4);
                mma_bf16(acc[j], a0, a1, a2, a3, b0, b1);
            }
        }

        // ---- acc -> accs (fragment layout) --------------------------------
#pragma unroll
        for (int j = 0; j < 4; j++) {
            const int dl = dwb + j * 8 + tg * 2;
            const int c = dl >> 4, u = dl & 15;
            *(float2*)&accs[c * 516 + (mb + g) * 16 + u] =
                make_float2(acc[j][0], acc[j][1]);
            *(float2*)&accs[c * 516 + (mb + g + 8) * 16 + u] =
                make_float2(acc[j][2], acc[j][3]);
        }
        __syncthreads();

        // ---- coalesced epilogue -------------------------------------------
        const float* __restrict__ maa =
            (f == 0) ? mk : (f == 1) ? mw : (f == 2) ? mv : (f == 3) ? mr : mg;
        float* __restrict__ op =
            out + ((size_t)grE * 5 + f) * D_DIM + d0 + ec * 16;
#pragma unroll
        for (int q = 0; q < 4; q++) {
            const float4 a  = *(const float4*)&accs[ec * 516 + er * 16 + q * 4];
            const float4 mm = *(const float4*)&maa[d0 + ec * 16 + q * 4];
            float4 o;
            o.x = cur4[q].x + (prv4[q].x - cur4[q].x) * (mm.x + a.x);
            o.y = cur4[q].y + (prv4[q].y - cur4[q].y) * (mm.y + a.y);
            o.z = cur4[q].z + (prv4[q].z - cur4[q].z) * (mm.z + a.z);
            o.w = cur4[q].w + (prv4[q].w - cur4[q].w) * (mm.w + a.w);
            *(float4*)&op[q * 4] = o;
        }
        // next iteration's first __syncthreads protects accs/W2s reuse
    }
}

// ---------------------------------------------------------------------------
// new_state = state with row i1 := x[:, S-1, :]
// ---------------------------------------------------------------------------
__global__ void new_state_kernel(
    const float* __restrict__ x, const float* __restrict__ state,
    const int* __restrict__ ip, float* __restrict__ outs, int total4)
{
    const int idx = blockIdx.x * blockDim.x + threadIdx.x;
    if (idx >= total4) return;
    const int e = idx * 4;
    const int d = e % D_DIM;
    const int r = (e / D_DIM) % NST;
    const int b = e / (D_DIM * NST);
    const int i1 = NST * ip[0] + 1;
    float4 v;
    if (r == i1)
        v = *(const float4*)&x[((size_t)b * S_LEN + (S_LEN - 1)) * D_DIM + d];
    else
        v = *(const float4*)&state[e];
    *(float4*)&outs[e] = v;
}

// ---------------------------------------------------------------------------
extern "C" void kernel_launch(void* const* d_in, const int* in_sizes, int n_in,
                              void* d_out, int out_size)
{
    const float* x   = (const float*)d_in[0];
    const float* st  = (const float*)d_in[1];
    const float* tmx = (const float*)d_in[2];
    const float* w1  = (const float*)d_in[3];
    const float* w2  = (const float*)d_in[4];
    const float* mk  = (const float*)d_in[5];
    const float* mw  = (const float*)d_in[6];
    const float* mv  = (const float*)d_in[7];
    const float* mr  = (const float*)d_in[8];
    const float* mg  = (const float*)d_in[9];
    const int*   ip  = (const int*)d_in[10];

    const int B    = in_sizes[0] / (S_LEN * D_DIM);
    const int rows = B * S_LEN;

    float* out       = (float*)d_out;
    float* out_state = out + (size_t)rows * 5 * D_DIM;

    // weight transposes (bf16)
    dim3 gw1(D_DIM / 32, NL / 32);
    w1t_kernel<<<gw1, 256>>>(w1);
    dim3 gw2(D_DIM / 32, 5);
    w2t_kernel<<<gw2, 256>>>(w2);

    // GEMM1 (HMMA) + tanh -> g_xxxh
    gemm1_mma_kernel<<<rows / 32, 256>>>(x, st, tmx, ip);

    // GEMM2 (HMMA) + fused epilogue
    dim3 g2(rows / 32, D_DIM / 128);
    gemm2_mma_kernel<<<g2, 256>>>(x, st, mk, mw, mv, mr, mg, ip, out);

    // new_state
    const int tot4 = B * NST * D_DIM / 4;
    new_state_kernel<<<(tot4 + 255) / 256, 256>>>(x, st, ip, out_state, tot4);
}